// round 1
// baseline (speedup 1.0000x reference)
#include <cuda_runtime.h>

// SparseMCFModel: the decoder softmax w = seg_softmax(pred_w[edge_row], edge_row)
// has identical logits within every segment (logit depends only on the segment
// key), so w[e] == 1/out_degree(edge_row[e]) exactly, independent of the GNN.
// Output flow therefore depends only on demands, edge_row, edge_col.
//
// Node-state reformulation of the 10-step scan:
//   x_1 = d_pos = relu(demands)
//   x_{t+1}[n] = d_pos[n] + sum_{e: col[e]=n} (1/deg[row[e]]) * x_t[row[e]]
//   flow[e]    = (1/deg[row[e]]) * x_10[row[e]]
//
// 3-buffer rotation lets each iteration be a single kernel: read x[cur],
// atomicAdd into x[nxt] (pre-reset to d_pos), and reset x[rst] for the
// iteration after next. Kernel boundaries provide the needed ordering.

#define N_NODES 20000
#define N_EDGES 200000

__device__ float g_dpos[N_NODES];
__device__ float g_x[3][N_NODES];
__device__ int   g_deg[N_NODES];

__global__ void k_init(const float* __restrict__ demands) {
    int i = blockIdx.x * blockDim.x + threadIdx.x;
    if (i < N_NODES) {
        float d = demands[i];
        d = d > 0.0f ? d : 0.0f;          // relu(demands)
        g_dpos[i] = d;
        g_x[0][i] = d;                    // x_1
        g_x[1][i] = d;                    // pre-reset buffer for first update
        g_deg[i]  = 0;
    }
}

__global__ void k_deg(const int* __restrict__ row) {
    int e = blockIdx.x * blockDim.x + threadIdx.x;
    if (e < N_EDGES) atomicAdd(&g_deg[row[e]], 1);
}

__global__ void k_update(const int* __restrict__ row, const int* __restrict__ col,
                         int cur, int nxt, int rst) {
    int i = blockIdx.x * blockDim.x + threadIdx.x;
    if (i < N_EDGES) {
        int r = __ldg(&row[i]);
        float w = 1.0f / (float)g_deg[r];         // exact: matches exp(0)/deg
        float v = w * g_x[cur][r];
        atomicAdd(&g_x[nxt][__ldg(&col[i])], v);
    }
    if (i < N_NODES) {
        g_x[rst][i] = g_dpos[i];                  // prep buffer for iter t+2
    }
}

__global__ void k_final(const int* __restrict__ row, float* __restrict__ out, int cur) {
    int e = blockIdx.x * blockDim.x + threadIdx.x;
    if (e < N_EDGES) {
        int r = __ldg(&row[e]);
        float w = 1.0f / (float)g_deg[r];
        out[e] = w * g_x[cur][r];
    }
}

extern "C" void kernel_launch(void* const* d_in, const int* in_sizes, int n_in,
                              void* d_out, int out_size) {
    // Input order: node_embeddings, demands, edge_row, edge_col, W_gat, a_src,
    //              a_dst, Wx, Wh, b_gru, Wd, bd
    const float* demands = (const float*)d_in[1];
    const int*   erow    = (const int*)d_in[2];
    const int*   ecol    = (const int*)d_in[3];

    const int bs = 256;
    const int gN = (N_NODES + bs - 1) / bs;
    const int gE = (N_EDGES + bs - 1) / bs;

    k_init<<<gN, bs>>>(demands);
    k_deg<<<gE, bs>>>(erow);

    // 9 node-state updates: x_1 -> x_10
    int cur = 0;
    for (int t = 0; t < 9; t++) {
        int nxt = (cur + 1) % 3;
        int rst = (cur + 2) % 3;
        k_update<<<gE, bs>>>(erow, ecol, cur, nxt, rst);
        cur = nxt;
    }

    // flow after 10 scan steps = w * x_10[row]
    k_final<<<gE, bs>>>(erow, (float*)d_out, cur);
}